// round 5
// baseline (speedup 1.0000x reference)
#include <cuda_runtime.h>
#include <math.h>

#define B  32
#define Q  1500
#define T  400
#define NC 10
#define ITERS 20
#define QC_V 8            // q-chunks for the K^T u matvec (fixed partial slots)
#define VCHUNK ((Q + QC_V - 1) / QC_V)   // 188
#define CQ 25             // q rows per cost block (60 * 25 = 1500 exact)

// ---------------- static device scratch (no cudaMalloc allowed) ----------------
__device__ float g_K[(size_t)B * Q * T];          // cost C, then K in place (76.8 MB)
__device__ float g_tab[(size_t)B * Q * NC];       // per-(b,q,class) focal cost
__device__ float g_u[(size_t)B * Q];
__device__ float g_vpart[(size_t)QC_V * B * T];   // deterministic partial sums of K^T u
__device__ float g_cmax[B];

__device__ __forceinline__ void atomicMaxFloat(float* addr, float v) {
    if (v >= 0.f) atomicMax((int*)addr, __float_as_int(v));
    else          atomicMin((unsigned int*)addr, __float_as_uint(v));
}

// ---------------- init: cmax = -inf, tgt_idx output as float32 ----------------
__global__ void k_init(float* out) {
    int b = blockIdx.x;
    if (threadIdx.x == 0) g_cmax[b] = -INFINITY;
    // tgt_idx: second output, f32 slots [B*T, 2*B*T)
    for (int t = threadIdx.x; t < T; t += blockDim.x)
        out[(size_t)B * T + (size_t)b * T + t] = (float)t;
}

// ---------------- per-(b,q) class-cost table ----------------
__global__ void k_tab(const float* __restrict__ logits) {
    int q = blockIdx.x * blockDim.x + threadIdx.x;
    int b = blockIdx.y;
    if (q >= Q) return;
    const float* lg = logits + ((size_t)b * Q + q) * NC;
    float*       tb = g_tab  + ((size_t)b * Q + q) * NC;
#pragma unroll
    for (int c = 0; c < NC; c++) {
        float x = lg[c];
        float p = 1.f / (1.f + expf(-x));                       // sigmoid
        float omp = 1.f - p;
        float pos = 0.25f * omp * omp * (-logf(p   + 1e-8f));   // ALPHA=0.25, GAMMA=2
        float neg = 0.75f * p   * p   * (-logf(omp + 1e-8f));
        tb[c] = pos - neg;                                       // cost_class
    }
}

// ---------------- cost matrix + per-batch max ----------------
__global__ void __launch_bounds__(416) k_cost(const float* __restrict__ pboxes,
                                              const int* __restrict__ labels,
                                              const float* __restrict__ tboxes) {
    int b   = blockIdx.y;
    int tid = threadIdx.x;           // 0..415, active t < 400
    int q0  = blockIdx.x * CQ;
    float lmax = -INFINITY;
    if (tid < T) {
        float4 tb = ((const float4*)(tboxes + (size_t)b * T * 4))[tid];
        int lab   = labels[(size_t)b * T + tid];                 // int32 (x64 disabled)
        lab = max(0, min(NC - 1, lab));                          // safety clamp
        const float4* pb4 = (const float4*)(pboxes + (size_t)b * Q * 4);
        for (int qi = 0; qi < CQ; qi++) {
            int q = q0 + qi;
            float4 pb = pb4[q];                                  // uniform per block iter
            float cc  = g_tab[((size_t)b * Q + q) * NC + lab];
            float dcx = pb.x - tb.x, dcy = pb.y - tb.y;
            float dw  = pb.z - tb.z, dh  = pb.w - tb.w;
            float l1  = fabsf(dcx) + fabsf(dcy) + fabsf(dw) + fabsf(dh);
            float hw = dw * 0.5f, hh = dh * 0.5f;
            float w2 = dcx * dcx + dcy * dcy + hw * hw + hh * hh;
            w2 = fmaxf(w2, 1e-7f);
            float nwd = expf(-sqrtf(w2) / 0.05f);
            float C = 5.f * l1 + cc + 5.f * (1.f - nwd);
            g_K[((size_t)b * Q + q) * T + tid] = C;
            lmax = fmaxf(lmax, C);
        }
    }
    // block max reduce (13 full warps)
#pragma unroll
    for (int o = 16; o; o >>= 1)
        lmax = fmaxf(lmax, __shfl_down_sync(0xffffffffu, lmax, o));
    __shared__ float wmax[13];
    int wid = tid >> 5, lane = tid & 31;
    if (lane == 0) wmax[wid] = lmax;
    __syncthreads();
    if (tid == 0) {
        float m = wmax[0];
#pragma unroll
        for (int i = 1; i < 13; i++) m = fmaxf(m, wmax[i]);
        atomicMaxFloat(&g_cmax[b], m);
    }
}

// ---------------- K = exp((cmax - C)/0.1) in place ----------------
__global__ void k_exp() {
    size_t i = (size_t)blockIdx.x * blockDim.x + threadIdx.x;
    if (i >= (size_t)B * Q * T) return;
    int b = (int)(i / ((size_t)Q * T));
    float c = g_K[i];
    g_K[i] = expf((g_cmax[b] - c) / 0.1f);   // overflows to +inf like the reference
}

// ---------------- u = 1/(K v + eps); warp per row, float4 coalesced ----------------
__global__ void __launch_bounds__(256) k_U(int it) {
    __shared__ float vs[T];
    int b = blockIdx.y;
    int tid = threadIdx.x;
    // reconstruct v from partials (fixed order -> deterministic); it==0 uses v0 = 1/T
    for (int t = tid; t < T; t += blockDim.x) {
        if (it == 0) {
            vs[t] = 1.0f / (float)T;
        } else {
            float s = 0.f;
#pragma unroll
            for (int qc = 0; qc < QC_V; qc++)
                s += g_vpart[((size_t)qc * B + b) * T + t];
            vs[t] = 1.0f / (s + 1e-6f);
        }
    }
    __syncthreads();
    int wid = tid >> 5, lane = tid & 31;
    int q = blockIdx.x * 8 + wid;
    if (q >= Q) return;
    const float4* row = (const float4*)(g_K + ((size_t)b * Q + q) * T);
    float acc = 0.f;
    for (int j = lane; j < T / 4; j += 32) {
        float4 k4 = row[j];
        int t = j * 4;
        acc += k4.x * vs[t] + k4.y * vs[t + 1] + k4.z * vs[t + 2] + k4.w * vs[t + 3];
    }
#pragma unroll
    for (int o = 16; o; o >>= 1) acc += __shfl_down_sync(0xffffffffu, acc, o);
    if (lane == 0) g_u[(size_t)b * Q + q] = 1.0f / (acc + 1e-6f);
}

// ---------------- partial K^T u; thread per column, coalesced across t ----------------
__global__ void __launch_bounds__(416) k_V() {
    __shared__ float us[VCHUNK];
    int b  = blockIdx.y;
    int qc = blockIdx.x;
    int q0 = qc * VCHUNK;
    int qn = min(VCHUNK, Q - q0);
    for (int i = threadIdx.x; i < qn; i += blockDim.x)
        us[i] = g_u[(size_t)b * Q + q0 + i];
    __syncthreads();
    int t = threadIdx.x;
    if (t >= T) return;
    const float* Kp = g_K + ((size_t)b * Q + q0) * T + t;
    float a0 = 0.f, a1 = 0.f, a2 = 0.f, a3 = 0.f;
    int i = 0;
    for (; i + 3 < qn; i += 4) {
        a0 += Kp[(size_t)(i + 0) * T] * us[i + 0];
        a1 += Kp[(size_t)(i + 1) * T] * us[i + 1];
        a2 += Kp[(size_t)(i + 2) * T] * us[i + 2];
        a3 += Kp[(size_t)(i + 3) * T] * us[i + 3];
    }
    for (; i < qn; i++) a0 += Kp[(size_t)i * T] * us[i];
    g_vpart[((size_t)qc * B + b) * T + t] = (a0 + a1) + (a2 + a3);
}

// ---------------- argmax over q of u*K*v with jnp NaN semantics ----------------
__global__ void __launch_bounds__(416) k_argmax(float* out) {
    __shared__ float us[Q];
    int b = blockIdx.x;
    for (int i = threadIdx.x; i < Q; i += blockDim.x)
        us[i] = g_u[(size_t)b * Q + i];
    __syncthreads();
    int t = threadIdx.x;
    if (t >= T) return;
    float s = 0.f;
#pragma unroll
    for (int qc = 0; qc < QC_V; qc++)
        s += g_vpart[((size_t)qc * B + b) * T + t];
    float v = 1.0f / (s + 1e-6f);
    const float* Kp = g_K + (size_t)b * Q * T + t;
    float best = -INFINITY;
    int   bq   = 0;
    bool  bnan = false;
    for (int q = 0; q < Q; q++) {
        float val = (us[q] * Kp[(size_t)q * T]) * v;   // (u[:,None]*K)*v order
        bool vn = (val != val);
        if (!bnan && (vn || val > best)) { best = val; bq = q; bnan = vn; }
    }
    out[(size_t)b * T + t] = (float)bq;                // src_idx: first output, f32
}

// ---------------- launch ----------------
extern "C" void kernel_launch(void* const* d_in, const int* in_sizes, int n_in,
                              void* d_out, int out_size) {
    const float* logits = (const float*)d_in[0];   // (B,Q,NC) f32
    const float* pboxes = (const float*)d_in[1];   // (B,Q,4)  f32
    const int*   labels = (const int*)d_in[2];     // (B,T)    int32 (x64 disabled)
    const float* tboxes = (const float*)d_in[3];   // (B,T,4)  f32
    float*       out    = (float*)d_out;           // f32: [0,BT)=src, [BT,2BT)=tgt

    k_init<<<B, 256>>>(out);
    k_tab<<<dim3((Q + 127) / 128, B), 128>>>(logits);
    k_cost<<<dim3(Q / CQ, B), 416>>>(pboxes, labels, tboxes);
    k_exp<<<(int)(((size_t)B * Q * T + 255) / 256), 256>>>();
    for (int it = 0; it < ITERS; it++) {
        k_U<<<dim3((Q + 7) / 8, B), 256>>>(it);
        k_V<<<dim3(QC_V, B), 416>>>();
    }
    k_argmax<<<B, 416>>>(out);
}

// round 6
// speedup vs baseline: 3.3396x; 3.3396x over previous
#include <cuda_runtime.h>
#include <math.h>

#define B  32
#define Q  1500
#define T  400
#define NC 10
#define ITERS 20
#define QC  37            // q-chunks for K^T u partials (32*37 = 1184 = 148*8 items)
#define QCH 41            // rows per chunk (37*41 >= 1500)
#define NBLK 148
#define NTHR 512
#define NWARP (NTHR/32)
#define TOTW (NBLK*NWARP)   // 2368 warps
#define GSTR (NBLK*NTHR)    // 75776 threads

// ---------------- static device scratch (no cudaMalloc allowed) ----------------
__device__ float g_K[(size_t)B * Q * T];      // cost C, then K in place (76.8 MB)
__device__ float g_tab[(size_t)B * Q * NC];   // per-(b,q,class) focal cost
__device__ float g_u[B * Q];
__device__ float g_v[B * T];
__device__ float g_vpart[(size_t)B * QC * T]; // deterministic fixed-slot partials
__device__ float g_cmax[B];
__device__ int   g_notnan[ITERS];
__device__ volatile unsigned g_bar_gen;       // monotonic across launches (self-consistent)
__device__ unsigned g_bar_cnt;

__device__ __forceinline__ void atomicMaxFloat(float* addr, float v) {
    if (v >= 0.f) atomicMax((int*)addr, __float_as_int(v));
    else          atomicMin((unsigned int*)addr, __float_as_uint(v));
}

// Sense-reversing grid barrier. Safe: grid = 148 blocks, 1 block/SM co-resident.
__device__ __forceinline__ void grid_barrier() {
    __syncthreads();
    if (threadIdx.x == 0) {
        __threadfence();                           // release prior writes
        unsigned gen = g_bar_gen;
        if (atomicAdd(&g_bar_cnt, 1u) == gridDim.x - 1) {
            g_bar_cnt = 0;
            __threadfence();
            g_bar_gen = gen + 1;                   // release
        } else {
            while (g_bar_gen == gen) { __nanosleep(64); }
        }
        __threadfence();                           // acquire
    }
    __syncthreads();
}

__global__ void __launch_bounds__(NTHR, 1)
k_all(const float* __restrict__ logits, const float* __restrict__ pboxes,
      const int*   __restrict__ labels, const float* __restrict__ tboxes,
      float* __restrict__ out)
{
    __shared__ float s_buf[Q];     // v-phase u-chunk (41) / argmax u row (1500)
    __shared__ int   s_flag;
    const int tid  = threadIdx.x;
    const int gtid = blockIdx.x * NTHR + tid;
    const int lane = tid & 31;
    const int gw   = gtid >> 5;    // global warp id

    // ---------------- phase 0: init + class-cost table ----------------
    if (gtid < ITERS) g_notnan[gtid] = 0;
    if (gtid >= 64 && gtid < 64 + B) g_cmax[gtid - 64] = -INFINITY;
    for (int i = gtid; i < B * T; i += GSTR) {
        out[B * T + i] = (float)(i % T);           // tgt_idx output (arange)
        g_v[i] = 1.0f / (float)T;                  // v0
    }
    for (int r = gtid; r < B * Q; r += GSTR) {
        const float* lg = logits + (size_t)r * NC;
        float*       tb = g_tab  + (size_t)r * NC;
#pragma unroll
        for (int c = 0; c < NC; c++) {
            float p   = 1.f / (1.f + expf(-lg[c]));
            float omp = 1.f - p;
            tb[c] = 0.25f * omp * omp * (-logf(p   + 1e-8f))
                  - 0.75f * p   * p   * (-logf(omp + 1e-8f));
        }
    }
    grid_barrier();

    // ---------------- phase A: cost matrix + per-batch max (warp per row) ----------------
    for (int r = gw; r < B * Q; r += TOTW) {
        int b = r / Q;
        float4 pb = ((const float4*)pboxes)[r];
        const float4* tb4  = (const float4*)tboxes + b * T;
        const int*    lb   = labels + b * T;
        const float*  tabr = g_tab + (size_t)r * NC;
        float*        kr   = g_K   + (size_t)r * T;
        float m = -INFINITY;
        for (int t = lane; t < T; t += 32) {
            float4 tb = tb4[t];
            float cc  = tabr[lb[t]];
            float dcx = pb.x - tb.x, dcy = pb.y - tb.y;
            float dw  = pb.z - tb.z, dh  = pb.w - tb.w;
            float l1  = fabsf(dcx) + fabsf(dcy) + fabsf(dw) + fabsf(dh);
            float w2  = dcx * dcx + dcy * dcy + 0.25f * dw * dw + 0.25f * dh * dh;
            w2 = fmaxf(w2, 1e-7f);
            float nwd = expf(-sqrtf(w2) * 20.0f);
            float C   = 5.f * l1 + cc + 5.f * (1.f - nwd);
            kr[t] = C;
            m = fmaxf(m, C);
        }
#pragma unroll
        for (int o = 16; o; o >>= 1) m = fmaxf(m, __shfl_down_sync(0xffffffffu, m, o));
        if (lane == 0) atomicMaxFloat(&g_cmax[b], m);
    }
    grid_barrier();

    // ---------------- phase B: K = exp((cmax - C)/0.1) in place, float4 ----------------
    {
        const int n4b = Q * T / 4;                 // 150000 per batch
        for (int b = 0; b < B; b++) {
            float cm = g_cmax[b];
            float4* p = (float4*)g_K + (size_t)b * n4b;
            for (int i = gtid; i < n4b; i += GSTR) {
                float4 c = p[i];
                c.x = expf((cm - c.x) * 10.f);     // overflows to +inf like reference
                c.y = expf((cm - c.y) * 10.f);
                c.z = expf((cm - c.z) * 10.f);
                c.w = expf((cm - c.w) * 10.f);
                p[i] = c;
            }
        }
    }
    grid_barrier();

    // ---------------- Sinkhorn loop with exact NaN fixed-point early exit ----------------
    bool flood = false;
    for (int it = 0; it < ITERS; it++) {
        // u = 1/(K v + eps): warp per row, float4
        if (tid == 0) s_flag = 0;
        __syncthreads();
        bool anyNot = false;
        for (int r = gw; r < B * Q; r += TOTW) {
            int b = r / Q;
            const float4* kr = (const float4*)(g_K + (size_t)r * T);
            const float4* v4 = (const float4*)(g_v + b * T);
            float acc = 0.f;
            for (int j = lane; j < T / 4; j += 32) {
                float4 k4 = kr[j]; float4 vv = v4[j];
                acc += k4.x * vv.x + k4.y * vv.y + k4.z * vv.z + k4.w * vv.w;
            }
#pragma unroll
            for (int o = 16; o; o >>= 1) acc += __shfl_down_sync(0xffffffffu, acc, o);
            if (lane == 0) {
                float u = 1.0f / (acc + 1e-6f);
                g_u[r] = u;
                if (u == u) anyNot = true;         // not NaN
            }
        }
        if (anyNot) s_flag = 1;                    // lane0 writers only; benign same-value race
        __syncthreads();
        if (tid == 0 && s_flag) atomicOr(&g_notnan[it], 1);
        grid_barrier();
        // all-NaN u is an exact fixed point: remaining iterations are no-ops
        if (g_notnan[it] == 0) { flood = true; break; }

        // K^T u partials: 8 fixed (b,qc) items per block, coalesced across t
        for (int k = 0; k < 8; k++) {
            int item = blockIdx.x * 8 + k;         // 0..1183
            int b = item / QC, qc = item % QC;
            int q0 = qc * QCH, qn = min(QCH, Q - q0);
            __syncthreads();
            if (tid < qn) s_buf[tid] = g_u[b * Q + q0 + tid];
            __syncthreads();
            if (tid < T) {
                const float* kp = g_K + ((size_t)(b * Q + q0)) * T + tid;
                float a0 = 0.f, a1 = 0.f, a2 = 0.f, a3 = 0.f;
                int i = 0;
                for (; i + 3 < qn; i += 4) {
                    a0 += kp[(size_t)(i + 0) * T] * s_buf[i + 0];
                    a1 += kp[(size_t)(i + 1) * T] * s_buf[i + 1];
                    a2 += kp[(size_t)(i + 2) * T] * s_buf[i + 2];
                    a3 += kp[(size_t)(i + 3) * T] * s_buf[i + 3];
                }
                for (; i < qn; i++) a0 += kp[(size_t)i * T] * s_buf[i];
                g_vpart[(size_t)item * T + tid] = (a0 + a1) + (a2 + a3);
            }
        }
        grid_barrier();

        // v = 1/(sum partials + eps), fixed summation order (deterministic)
        for (int i = gtid; i < B * T; i += GSTR) {
            int b = i / T, t = i - b * T;
            float s = 0.f;
#pragma unroll
            for (int qc = 0; qc < QC; qc++)
                s += g_vpart[(size_t)(b * QC + qc) * T + t];
            g_v[i] = 1.0f / (s + 1e-6f);
        }
        grid_barrier();
    }

    // ---------------- final: src_idx ----------------
    if (flood) {
        // P is all-NaN -> jnp.argmax returns 0 everywhere (first occurrence)
        for (int i = gtid; i < B * T; i += GSTR) out[i] = 0.f;
    } else {
        // full argmax over q of u*K*v with jnp NaN semantics (slow path)
        if (blockIdx.x < B) {
            int b = blockIdx.x;
            for (int i = tid; i < Q; i += NTHR) s_buf[i] = g_u[b * Q + i];
            __syncthreads();
            if (tid < T) {
                float v = g_v[b * T + tid];
                const float* kp = g_K + (size_t)b * Q * T + tid;
                float best = -INFINITY; int bq = 0; bool bnan = false;
                for (int q = 0; q < Q; q++) {
                    float val = (s_buf[q] * kp[(size_t)q * T]) * v;
                    bool vn = (val != val);
                    if (!bnan && (vn || val > best)) { best = val; bq = q; bnan = vn; }
                }
                out[b * T + tid] = (float)bq;
            }
        }
    }
}

// ---------------- launch: ONE persistent kernel ----------------
extern "C" void kernel_launch(void* const* d_in, const int* in_sizes, int n_in,
                              void* d_out, int out_size) {
    const float* logits = (const float*)d_in[0];   // (B,Q,NC) f32
    const float* pboxes = (const float*)d_in[1];   // (B,Q,4)  f32
    const int*   labels = (const int*)d_in[2];     // (B,T)    int32
    const float* tboxes = (const float*)d_in[3];   // (B,T,4)  f32
    float*       out    = (float*)d_out;           // f32: [0,BT)=src, [BT,2BT)=tgt

    k_all<<<NBLK, NTHR>>>(logits, pboxes, labels, tboxes, out);
}

// round 7
// speedup vs baseline: 8.4510x; 2.5305x over previous
#include <cuda_runtime.h>
#include <math.h>

#define B  32
#define Q  1500
#define T  400
#define NC 10
#define ITERS 20
#define QC  37                 // q-chunks for K^T u partials: B*QC = 1184 = 148*8
#define QCH 41                 // rows per chunk (37*41 >= 1500)
#define SBLK 148
#define STHR 1024
#define SWARPS (SBLK * STHR / 32)    // 4736
#define SSTR   (SBLK * STHR)         // 151552

// ---------------- static device scratch (no cudaMalloc allowed) ----------------
__device__ float g_K[(size_t)B * Q * T];      // cost C, then K in place (76.8 MB)
__device__ float g_tab[(size_t)B * Q * NC];   // per-(b,q,class) focal cost
__device__ float g_u[B * Q];
__device__ float g_v[B * T];
__device__ float g_vpart[(size_t)B * QC * T]; // deterministic fixed-slot partials
__device__ float g_cmax[B];
__device__ int   g_notnan[ITERS];
__device__ volatile unsigned g_bar_gen;       // monotonic across replays (self-consistent)
__device__ unsigned g_bar_cnt;

__device__ __forceinline__ void atomicMaxFloat(float* addr, float v) {
    if (v >= 0.f) atomicMax((int*)addr, __float_as_int(v));
    else          atomicMin((unsigned int*)addr, __float_as_uint(v));
}

// ---------------- kernel 1: init + class-cost table (full occupancy) ----------------
__global__ void k_prep(const float* __restrict__ logits, float* __restrict__ out) {
    int gtid = blockIdx.x * blockDim.x + threadIdx.x;
    int gs   = gridDim.x * blockDim.x;
    if (gtid < ITERS) g_notnan[gtid] = 0;
    if (gtid >= 64 && gtid < 64 + B) g_cmax[gtid - 64] = -INFINITY;
    for (int i = gtid; i < B * T; i += gs) {
        out[B * T + i] = (float)(i % T);           // tgt_idx output (arange)
        g_v[i] = 1.0f / (float)T;                  // v0
    }
    for (int r = gtid; r < B * Q; r += gs) {
        const float* lg = logits + (size_t)r * NC;
        float*       tb = g_tab  + (size_t)r * NC;
#pragma unroll
        for (int c = 0; c < NC; c++) {
            float p   = 1.f / (1.f + expf(-lg[c]));
            float omp = 1.f - p;
            tb[c] = 0.25f * omp * omp * (-logf(p   + 1e-8f))
                  - 0.75f * p   * p   * (-logf(omp + 1e-8f));
        }
    }
}

// ---------------- kernel 2: cost matrix + per-batch max (warp per row) ----------------
// grid: 3000 blocks x 512 -> exactly one warp per (b,q) row
__global__ void __launch_bounds__(512) k_cost(const float* __restrict__ pboxes,
                                              const int*   __restrict__ labels,
                                              const float* __restrict__ tboxes) {
    int r    = blockIdx.x * 16 + (threadIdx.x >> 5);   // row = global warp id
    int lane = threadIdx.x & 31;
    int b    = r / Q;
    float4 pb = ((const float4*)pboxes)[r];
    const float4* tb4  = (const float4*)tboxes + b * T;
    const int*    lb   = labels + b * T;
    const float*  tabr = g_tab + (size_t)r * NC;
    float*        kr   = g_K   + (size_t)r * T;
    float m = -INFINITY;
#pragma unroll
    for (int k = 0; k < 13; k++) {
        int t = lane + k * 32;
        if (t < T) {
            float4 tb = tb4[t];
            float cc  = tabr[lb[t]];
            float dcx = pb.x - tb.x, dcy = pb.y - tb.y;
            float dw  = pb.z - tb.z, dh  = pb.w - tb.w;
            float l1  = fabsf(dcx) + fabsf(dcy) + fabsf(dw) + fabsf(dh);
            float w2  = dcx * dcx + dcy * dcy + 0.25f * dw * dw + 0.25f * dh * dh;
            w2 = fmaxf(w2, 1e-7f);
            float nwd = expf(-sqrtf(w2) * 20.0f);
            float C   = 5.f * l1 + cc + 5.f * (1.f - nwd);
            kr[t] = C;
            m = fmaxf(m, C);
        }
    }
#pragma unroll
    for (int o = 16; o; o >>= 1) m = fmaxf(m, __shfl_down_sync(0xffffffffu, m, o));
    if (lane == 0) atomicMaxFloat(&g_cmax[b], m);
}

// ---------------- kernel 3: K = exp((cmax-C)*10) in place, fused u0 = 1/(K v0+eps) ----------------
// grid: 3000 blocks x 512 -> one warp per row; float4 coalesced
__global__ void __launch_bounds__(512) k_expu() {
    int r    = blockIdx.x * 16 + (threadIdx.x >> 5);
    int lane = threadIdx.x & 31;
    int b    = r / Q;
    float cm = g_cmax[b];
    const float invT = 1.0f / (float)T;
    float4* kr = (float4*)(g_K + (size_t)r * T);
    float acc = 0.f;
#pragma unroll
    for (int k = 0; k < 4; k++) {
        int j = lane + k * 32;
        if (j < T / 4) {
            float4 c = kr[j];
            c.x = expf((cm - c.x) * 10.f);         // overflows to +inf like reference
            c.y = expf((cm - c.y) * 10.f);
            c.z = expf((cm - c.z) * 10.f);
            c.w = expf((cm - c.w) * 10.f);
            kr[j] = c;
            acc += c.x * invT + c.y * invT + c.z * invT + c.w * invT;
        }
    }
#pragma unroll
    for (int o = 16; o; o >>= 1) acc += __shfl_down_sync(0xffffffffu, acc, o);
    if (lane == 0) g_u[r] = 1.0f / (acc + 1e-6f);  // u after iteration 1
}

// ---------------- grid barrier (148 co-resident blocks) ----------------
__device__ __forceinline__ void grid_barrier() {
    __syncthreads();
    if (threadIdx.x == 0) {
        __threadfence();
        unsigned gen = g_bar_gen;
        if (atomicAdd(&g_bar_cnt, 1u) == gridDim.x - 1) {
            g_bar_cnt = 0;
            __threadfence();
            g_bar_gen = gen + 1;
        } else {
            while (g_bar_gen == gen) { __nanosleep(64); }
        }
        __threadfence();
    }
    __syncthreads();
}

// ---------------- kernel 4: persistent Sinkhorn loop + output ----------------
__global__ void __launch_bounds__(STHR, 1)
k_sink(float* __restrict__ out)
{
    __shared__ float s_buf[Q];       // argmax u row; vpart u-chunks at [0],[64]
    __shared__ int   s_flag;
    const int tid  = threadIdx.x;
    const int gtid = blockIdx.x * STHR + tid;
    const int lane = tid & 31;
    const int gw   = gtid >> 5;
    const int sub  = tid >> 9;       // half-block id (0/1)
    const int stid = tid & 511;

    bool flood = false;
    for (int it = 1; it < ITERS; it++) {
        // ---- vpart: K^T u, 8 fixed items per block (2 halves x 4 rounds) ----
        for (int k = 0; k < 4; k++) {
            int item = blockIdx.x * 8 + k * 2 + sub;       // 0..1183
            int b = item / QC, qc = item % QC;
            int q0 = qc * QCH, qn = min(QCH, Q - q0);
            __syncthreads();
            if (stid < qn) s_buf[sub * 64 + stid] = g_u[b * Q + q0 + stid];
            __syncthreads();
            if (stid < T) {
                const float* kp = g_K + (size_t)(b * Q + q0) * T + stid;
                const float* uu = s_buf + sub * 64;
                float a0 = 0.f, a1 = 0.f, a2 = 0.f, a3 = 0.f;
                int i = 0;
                for (; i + 3 < qn; i += 4) {
                    a0 += kp[(size_t)(i + 0) * T] * uu[i + 0];
                    a1 += kp[(size_t)(i + 1) * T] * uu[i + 1];
                    a2 += kp[(size_t)(i + 2) * T] * uu[i + 2];
                    a3 += kp[(size_t)(i + 3) * T] * uu[i + 3];
                }
                for (; i < qn; i++) a0 += kp[(size_t)i * T] * uu[i];
                g_vpart[(size_t)item * T + stid] = (a0 + a1) + (a2 + a3);
            }
        }
        grid_barrier();
        // ---- v = 1/(sum partials + eps), fixed order ----
        for (int i = gtid; i < B * T; i += SSTR) {
            int b = i / T, t = i - b * T;
            float s = 0.f;
#pragma unroll
            for (int qc = 0; qc < QC; qc++)
                s += g_vpart[(size_t)(b * QC + qc) * T + t];
            g_v[i] = 1.0f / (s + 1e-6f);
        }
        grid_barrier();
        // ---- u = 1/(K v + eps), warp per row + NaN detect ----
        if (tid == 0) s_flag = 0;
        __syncthreads();
        bool anyNot = false;
        for (int r = gw; r < B * Q; r += SWARPS) {
            int b = r / Q;
            const float4* kr = (const float4*)(g_K + (size_t)r * T);
            const float4* v4 = (const float4*)(g_v + b * T);
            float acc = 0.f;
#pragma unroll
            for (int k = 0; k < 4; k++) {
                int j = lane + k * 32;
                if (j < T / 4) {
                    float4 k4 = kr[j]; float4 vv = v4[j];
                    acc += k4.x * vv.x + k4.y * vv.y + k4.z * vv.z + k4.w * vv.w;
                }
            }
#pragma unroll
            for (int o = 16; o; o >>= 1) acc += __shfl_down_sync(0xffffffffu, acc, o);
            if (lane == 0) {
                float u = 1.0f / (acc + 1e-6f);
                g_u[r] = u;
                if (u == u) anyNot = true;
            }
        }
        if (anyNot) s_flag = 1;
        __syncthreads();
        if (tid == 0 && s_flag) atomicOr(&g_notnan[it], 1);
        grid_barrier();
        // all-NaN u is an exact fixed point of the iteration -> remaining steps no-ops
        if (g_notnan[it] == 0) { flood = true; break; }
    }

    if (flood) {
        // P = u*K*v is all-NaN -> jnp.argmax (NaN = max, first occurrence) = 0
        for (int i = gtid; i < B * T; i += SSTR) out[i] = 0.f;
        return;
    }

    // ---- non-flood: final v update (v20), then exact argmax with jnp NaN semantics ----
    for (int k = 0; k < 4; k++) {
        int item = blockIdx.x * 8 + k * 2 + sub;
        int b = item / QC, qc = item % QC;
        int q0 = qc * QCH, qn = min(QCH, Q - q0);
        __syncthreads();
        if (stid < qn) s_buf[sub * 64 + stid] = g_u[b * Q + q0 + stid];
        __syncthreads();
        if (stid < T) {
            const float* kp = g_K + (size_t)(b * Q + q0) * T + stid;
            const float* uu = s_buf + sub * 64;
            float a = 0.f;
            for (int i = 0; i < qn; i++) a += kp[(size_t)i * T] * uu[i];
            g_vpart[(size_t)item * T + stid] = a;
        }
    }
    grid_barrier();
    for (int i = gtid; i < B * T; i += SSTR) {
        int b = i / T, t = i - b * T;
        float s = 0.f;
#pragma unroll
        for (int qc = 0; qc < QC; qc++)
            s += g_vpart[(size_t)(b * QC + qc) * T + t];
        g_v[i] = 1.0f / (s + 1e-6f);
    }
    grid_barrier();
    if (blockIdx.x < B) {
        int b = blockIdx.x;
        for (int i = tid; i < Q; i += STHR) s_buf[i] = g_u[b * Q + i];
        __syncthreads();
        if (tid < T) {
            float v = g_v[b * T + tid];
            const float* kp = g_K + (size_t)b * Q * T + tid;
            float best = -INFINITY; int bq = 0; bool bnan = false;
            for (int q = 0; q < Q; q++) {
                float val = (s_buf[q] * kp[(size_t)q * T]) * v;
                bool vn = (val != val);
                if (!bnan && (vn || val > best)) { best = val; bq = q; bnan = vn; }
            }
            out[b * T + tid] = (float)bq;
        }
    }
}

// ---------------- launch ----------------
extern "C" void kernel_launch(void* const* d_in, const int* in_sizes, int n_in,
                              void* d_out, int out_size) {
    const float* logits = (const float*)d_in[0];   // (B,Q,NC) f32
    const float* pboxes = (const float*)d_in[1];   // (B,Q,4)  f32
    const int*   labels = (const int*)d_in[2];     // (B,T)    int32
    const float* tboxes = (const float*)d_in[3];   // (B,T,4)  f32
    float*       out    = (float*)d_out;           // f32: [0,BT)=src, [BT,2BT)=tgt

    k_prep<<<192, 256>>>(logits, out);
    k_cost<<<3000, 512>>>(pboxes, labels, tboxes);
    k_expu<<<3000, 512>>>();
    k_sink<<<SBLK, STHR>>>(out);
}

// round 9
// speedup vs baseline: 11.7300x; 1.3880x over previous
#include <cuda_runtime.h>
#include <math.h>

#define B  32
#define Q  1500
#define T  400
#define NC 10
#define ITERS 20
#define RPB 20                  // rows per block in fused exp kernel
#define BPB 75                  // blocks per batch (Q/RPB)
#define FBLK 148
#define FTHR 1024
#define FSTR  (FBLK*FTHR)
#define FWARPS (FSTR/32)
#define QC  37                  // fallback vpart chunks (B*QC = 1184 = 148*8)
#define QCH 41

// ---------------- static device scratch (no cudaMalloc) ----------------
__device__ float g_K[(size_t)B * Q * T];   // holds cost C permanently (K recomputed on demand)
__device__ float g_u[B * Q];
__device__ float g_v[B * T];
__device__ float g_vpart[B * BPB * T];     // 960000 floats; fallback reuses (needs 473600)
__device__ float g_cmax[B];
__device__ int   g_flag;                   // any non-NaN v1 -> fallback
__device__ int   g_notnan[ITERS];
__device__ volatile unsigned g_bar_gen;    // monotonic across replays (self-consistent)
__device__ unsigned g_bar_cnt;

__device__ __forceinline__ void atomicMaxFloat(float* addr, float v) {
    if (v >= 0.f) atomicMax((int*)addr, __float_as_int(v));
    else          atomicMin((unsigned int*)addr, __float_as_uint(v));
}

// ---------------- kernel 1: tiny per-replay init ----------------
__global__ void k_prep() {
    int t = threadIdx.x;
    if (t < B) g_cmax[t] = -INFINITY;
    if (t < ITERS) g_notnan[t] = 0;
    if (t == 63) g_flag = 0;
}

// ---------------- kernel 2: cost matrix + per-batch max (warp per row) ----------------
// grid 3000 x 512: one warp per (b,q) row. Class cost via lane shuffle (no table array).
__global__ void __launch_bounds__(512) k_cost(const float* __restrict__ logits,
                                              const float* __restrict__ pboxes,
                                              const int*   __restrict__ labels,
                                              const float* __restrict__ tboxes) {
    int r    = blockIdx.x * 16 + (threadIdx.x >> 5);
    int lane = threadIdx.x & 31;
    int b    = r / Q;
    // focal class cost for this row, one class per lane (lanes 0..9)
    float tabv = 0.f;
    if (lane < NC) {
        float x   = logits[(size_t)r * NC + lane];
        float p   = 1.f / (1.f + expf(-x));
        float omp = 1.f - p;
        tabv = 0.25f * omp * omp * (-logf(p   + 1e-8f))
             - 0.75f * p   * p   * (-logf(omp + 1e-8f));
    }
    float4 pb = ((const float4*)pboxes)[r];
    const float4* tb4 = (const float4*)tboxes + b * T;
    const int*    lb  = labels + b * T;
    float*        kr  = g_K + (size_t)r * T;
    float m = -INFINITY;
#pragma unroll
    for (int k = 0; k < 13; k++) {
        int t = lane + k * 32;
        // ALL lanes execute the shuffle (UB otherwise); inactive lanes use lab=0
        int lab = (t < T) ? lb[t] : 0;
        lab = max(0, min(NC - 1, lab));
        float cc = __shfl_sync(0xffffffffu, tabv, lab);
        if (t < T) {
            float4 tb = tb4[t];
            float dcx = pb.x - tb.x, dcy = pb.y - tb.y;
            float dw  = pb.z - tb.z, dh  = pb.w - tb.w;
            float l1  = fabsf(dcx) + fabsf(dcy) + fabsf(dw) + fabsf(dh);
            float w2  = dcx * dcx + dcy * dcy + 0.25f * dw * dw + 0.25f * dh * dh;
            w2 = fmaxf(w2, 1e-7f);
            float nwd = expf(-sqrtf(w2) * 20.0f);
            float C   = 5.f * l1 + cc + 5.f * (1.f - nwd);
            kr[t] = C;
            m = fmaxf(m, C);
        }
    }
#pragma unroll
    for (int o = 16; o; o >>= 1) m = fmaxf(m, __shfl_down_sync(0xffffffffu, m, o));
    if (lane == 0) atomicMaxFloat(&g_cmax[b], m);
}

// ---------------- kernel 3: fused exp + u1 + partial K^T u1 (K lives only in smem) ----------------
// grid 2400 x 640: block = 20 rows of one batch; smem tile 20x400 f32 (32 KB)
__global__ void __launch_bounds__(640, 2) k_fuse() {
    __shared__ float sK[RPB * T];
    __shared__ float su[RPB];
    const int tid  = threadIdx.x;
    const int w    = tid >> 5;          // 0..19
    const int lane = tid & 31;
    const int b    = blockIdx.x / BPB;
    const int blk  = blockIdx.x % BPB;
    const int r    = b * Q + blk * RPB + w;
    const float cm   = g_cmax[b];
    const float invT = 1.0f / (float)T;

    const float4* cr = (const float4*)(g_K + (size_t)r * T);
    float4* skr = (float4*)(sK + w * T);
    float acc = 0.f;
#pragma unroll
    for (int kk = 0; kk < 4; kk++) {
        int j = lane + kk * 32;
        if (j < T / 4) {
            float4 c = cr[j];
            float4 k;
            k.x = expf((cm - c.x) * 10.f);   // overflows to +inf like reference
            k.y = expf((cm - c.y) * 10.f);
            k.z = expf((cm - c.z) * 10.f);
            k.w = expf((cm - c.w) * 10.f);
            skr[j] = k;
            // element-wise * (1/T) to match reference K@v0 overflow semantics
            acc += k.x * invT + k.y * invT + k.z * invT + k.w * invT;
        }
    }
#pragma unroll
    for (int o = 16; o; o >>= 1) acc += __shfl_down_sync(0xffffffffu, acc, o);
    if (lane == 0) {
        float u = 1.0f / (acc + 1e-6f);      // u after iteration 1
        su[w] = u;
        g_u[r] = u;
    }
    __syncthreads();
    // partial column sums over this block's 20 rows, fixed order (deterministic)
    if (tid < T) {
        float s = 0.f;
#pragma unroll
        for (int w2 = 0; w2 < RPB; w2++)
            s += sK[w2 * T + tid] * su[w2];  // inf*0 -> NaN, exactly as reference
        g_vpart[(b * BPB + blk) * T + tid] = s;
    }
}

// ---------------- kernel 4: v1 = 1/(colsum+eps), flood certificate, tgt output ----------------
__global__ void __launch_bounds__(416) k_vred(float* __restrict__ out) {
    __shared__ int s_flag;
    int b = blockIdx.x, t = threadIdx.x;
    if (t == 0) s_flag = 0;
    __syncthreads();
    if (t < T) {
        float s = 0.f;
#pragma unroll 5
        for (int k = 0; k < BPB; k++)
            s += g_vpart[(b * BPB + k) * T + t];
        float v = 1.0f / (s + 1e-6f);
        g_v[b * T + t] = v;
        out[B * T + b * T + t] = (float)t;       // tgt_idx (arange)
        if (v == v) s_flag = 1;                  // non-NaN exists
    }
    __syncthreads();
    if (t == 0 && s_flag) atomicOr(&g_flag, 1);
}

// ---------------- grid barrier (148 co-resident blocks) ----------------
__device__ __forceinline__ void grid_barrier() {
    __syncthreads();
    if (threadIdx.x == 0) {
        __threadfence();
        unsigned gen = g_bar_gen;
        if (atomicAdd(&g_bar_cnt, 1u) == gridDim.x - 1) {
            g_bar_cnt = 0;
            __threadfence();
            g_bar_gen = gen + 1;
        } else {
            while (g_bar_gen == gen) { __nanosleep(64); }
        }
        __threadfence();
    }
    __syncthreads();
}

__device__ __forceinline__ float kval(float cm, float c) { return expf((cm - c) * 10.f); }

// ---------------- kernel 5: flood output OR exact fallback (recomputes K from C) ----------------
__global__ void __launch_bounds__(FTHR, 1) k_final(float* __restrict__ out) {
    __shared__ float s_buf[Q];
    __shared__ int   s_flag;
    const int tid  = threadIdx.x;
    const int gtid = blockIdx.x * FTHR + tid;
    const int lane = tid & 31;
    const int gw   = gtid >> 5;

    if (g_flag == 0) {
        // v1 all-NaN -> exact fixed point -> P all-NaN -> jnp.argmax = 0 everywhere
        for (int i = gtid; i < B * T; i += FSTR) out[i] = 0.f;
        return;
    }

    // ---- exact fallback: 19 more (u,v) pairs, K recomputed from C ----
    bool flood = false;
    for (int it = 1; it < ITERS; it++) {
        if (tid == 0) s_flag = 0;
        __syncthreads();
        bool anyNot = false;
        for (int r = gw; r < B * Q; r += FWARPS) {
            int b = r / Q;
            float cm = g_cmax[b];
            const float4* cr = (const float4*)(g_K + (size_t)r * T);
            const float4* v4 = (const float4*)(g_v + b * T);
            float acc = 0.f;
#pragma unroll
            for (int kk = 0; kk < 4; kk++) {
                int j = lane + kk * 32;
                if (j < T / 4) {
                    float4 c = cr[j]; float4 vv = v4[j];
                    acc += kval(cm, c.x) * vv.x + kval(cm, c.y) * vv.y
                         + kval(cm, c.z) * vv.z + kval(cm, c.w) * vv.w;
                }
            }
#pragma unroll
            for (int o = 16; o; o >>= 1) acc += __shfl_down_sync(0xffffffffu, acc, o);
            if (lane == 0) {
                float u = 1.0f / (acc + 1e-6f);
                g_u[r] = u;
                if (u == u) anyNot = true;
            }
        }
        if (anyNot) s_flag = 1;
        __syncthreads();
        if (tid == 0 && s_flag) atomicOr(&g_notnan[it], 1);
        grid_barrier();
        if (g_notnan[it] == 0) { flood = true; break; }   // all-NaN u fixed point

        // vpart: K^T u, 8 fixed chunks per block
        for (int k = 0; k < 8; k++) {
            int item = blockIdx.x * 8 + k;                 // 0..1183
            int b = item / QC, qc = item % QC;
            int q0 = qc * QCH, qn = min(QCH, Q - q0);
            __syncthreads();
            if (tid < qn) s_buf[tid] = g_u[b * Q + q0 + tid];
            __syncthreads();
            if (tid < T) {
                float cm = g_cmax[b];
                const float* cp = g_K + (size_t)(b * Q + q0) * T + tid;
                float a = 0.f;
                for (int i = 0; i < qn; i++)
                    a += kval(cm, cp[(size_t)i * T]) * s_buf[i];
                g_vpart[item * T + tid] = a;
            }
        }
        grid_barrier();
        for (int i = gtid; i < B * T; i += FSTR) {
            int b = i / T, t = i - b * T;
            float s = 0.f;
#pragma unroll
            for (int qc = 0; qc < QC; qc++)
                s += g_vpart[(b * QC + qc) * T + t];
            g_v[i] = 1.0f / (s + 1e-6f);
        }
        grid_barrier();
    }

    if (flood) {
        for (int i = gtid; i < B * T; i += FSTR) out[i] = 0.f;
        return;
    }

    // exact argmax over q of u*K*v with jnp NaN semantics (first occurrence)
    if (blockIdx.x < B) {
        int b = blockIdx.x;
        float cm = g_cmax[b];
        for (int i = tid; i < Q; i += FTHR) s_buf[i] = g_u[b * Q + i];
        __syncthreads();
        if (tid < T) {
            float v = g_v[b * T + tid];
            const float* cp = g_K + (size_t)b * Q * T + tid;
            float best = -INFINITY; int bq = 0; bool bnan = false;
            for (int q = 0; q < Q; q++) {
                float val = (s_buf[q] * kval(cm, cp[(size_t)q * T])) * v;
                bool vn = (val != val);
                if (!bnan && (vn || val > best)) { best = val; bq = q; bnan = vn; }
            }
            out[b * T + tid] = (float)bq;
        }
    }
}

// ---------------- launch ----------------
extern "C" void kernel_launch(void* const* d_in, const int* in_sizes, int n_in,
                              void* d_out, int out_size) {
    const float* logits = (const float*)d_in[0];   // (B,Q,NC) f32
    const float* pboxes = (const float*)d_in[1];   // (B,Q,4)  f32
    const int*   labels = (const int*)d_in[2];     // (B,T)    int32
    const float* tboxes = (const float*)d_in[3];   // (B,T,4)  f32
    float*       out    = (float*)d_out;           // f32: [0,BT)=src, [BT,2BT)=tgt

    k_prep<<<1, 64>>>();
    k_cost<<<3000, 512>>>(logits, pboxes, labels, tboxes);
    k_fuse<<<B * BPB, 640>>>();
    k_vred<<<B, 416>>>(out);
    k_final<<<FBLK, FTHR>>>(out);
}

// round 10
// speedup vs baseline: 12.7223x; 1.0846x over previous
#include <cuda_runtime.h>
#include <math.h>

#define B  32
#define Q  1500
#define T  400
#define NC 10
#define ITERS 20
#define RPB 20                  // rows per smem tile in fused kernel
#define GPB 3                   // row-groups per fuse block
#define CPB 25                  // vpart chunks per batch (Q / (RPB*GPB))
#define FBLK 148
#define FTHR 1024
#define FSTR  (FBLK*FTHR)
#define FWARPS (FSTR/32)
#define QC  37                  // fallback vpart chunks (B*QC = 1184 = 148*8)
#define QCH 41

// ---------------- static device scratch (no cudaMalloc) ----------------
__device__ float g_K[(size_t)B * Q * T];   // holds cost C permanently (K recomputed on demand)
__device__ float g_u[B * Q];
__device__ float g_v[B * T];
__device__ float g_vpart[B * QC * T];      // 473600 floats: fits fast path (B*25*T) and fallback
__device__ float g_cmax[B];
__device__ int   g_flag;                   // any non-NaN v1 -> fallback
__device__ int   g_notnan[ITERS];
__device__ volatile unsigned g_bar_gen;    // monotonic across replays (self-consistent)
__device__ unsigned g_bar_cnt;

__device__ __forceinline__ void atomicMaxFloat(float* addr, float v) {
    if (v >= 0.f) atomicMax((int*)addr, __float_as_int(v));
    else          atomicMin((unsigned int*)addr, __float_as_uint(v));
}

// ---------------- kernel 1: tiny per-replay init ----------------
__global__ void k_prep() {
    int t = threadIdx.x;
    if (t < B) g_cmax[t] = -INFINITY;
    if (t < ITERS) g_notnan[t] = 0;
    if (t == 63) g_flag = 0;
}

// ---------------- kernel 2: cost matrix + per-batch max (warp per row) ----------------
__global__ void __launch_bounds__(512) k_cost(const float* __restrict__ logits,
                                              const float* __restrict__ pboxes,
                                              const int*   __restrict__ labels,
                                              const float* __restrict__ tboxes) {
    int r    = blockIdx.x * 16 + (threadIdx.x >> 5);
    int lane = threadIdx.x & 31;
    int b    = r / Q;
    // focal class cost for this row, one class per lane (lanes 0..9)
    float tabv = 0.f;
    if (lane < NC) {
        float x   = logits[(size_t)r * NC + lane];
        float p   = 1.f / (1.f + expf(-x));
        float omp = 1.f - p;
        tabv = 0.25f * omp * omp * (-logf(p   + 1e-8f))
             - 0.75f * p   * p   * (-logf(omp + 1e-8f));
    }
    float4 pb = ((const float4*)pboxes)[r];
    const float4* tb4 = (const float4*)tboxes + b * T;
    const int*    lb  = labels + b * T;
    float*        kr  = g_K + (size_t)r * T;
    float m = -INFINITY;
#pragma unroll
    for (int k = 0; k < 13; k++) {
        int t = lane + k * 32;
        // ALL lanes execute the shuffle (UB otherwise); inactive lanes use lab=0
        int lab = (t < T) ? lb[t] : 0;
        lab = max(0, min(NC - 1, lab));
        float cc = __shfl_sync(0xffffffffu, tabv, lab);
        if (t < T) {
            float4 tb = tb4[t];
            float dcx = pb.x - tb.x, dcy = pb.y - tb.y;
            float dw  = pb.z - tb.z, dh  = pb.w - tb.w;
            float l1  = fabsf(dcx) + fabsf(dcy) + fabsf(dw) + fabsf(dh);
            float w2  = dcx * dcx + dcy * dcy + 0.25f * dw * dw + 0.25f * dh * dh;
            w2 = fmaxf(w2, 1e-7f);
            float nwd = expf(-sqrtf(w2) * 20.0f);
            float C   = 5.f * l1 + cc + 5.f * (1.f - nwd);
            kr[t] = C;
            m = fmaxf(m, C);
        }
    }
#pragma unroll
    for (int o = 16; o; o >>= 1) m = fmaxf(m, __shfl_down_sync(0xffffffffu, m, o));
    if (lane == 0) atomicMaxFloat(&g_cmax[b], m);
}

// ---------------- kernel 3: fused exp + u1 + K^T u1 partials (3 groups/block) ----------------
// grid 800 x 640: block = 60 rows of one batch (3 x 20-row smem tiles); K never hits global
__global__ void __launch_bounds__(640, 2) k_fuse() {
    __shared__ float sK[RPB * T];
    __shared__ float su[RPB];
    const int tid  = threadIdx.x;
    const int w    = tid >> 5;          // 0..19
    const int lane = tid & 31;
    const int b    = blockIdx.x / CPB;
    const int blk  = blockIdx.x % CPB;
    const int rbase = b * Q + blk * (RPB * GPB);
    const float cm   = g_cmax[b];
    const float invT = 1.0f / (float)T;

    float vacc = 0.f;
#pragma unroll
    for (int g = 0; g < GPB; g++) {
        int r = rbase + g * RPB + w;
        const float4* cr = (const float4*)(g_K + (size_t)r * T);
        float4* skr = (float4*)(sK + w * T);
        float acc = 0.f;
#pragma unroll
        for (int kk = 0; kk < 4; kk++) {
            int j = lane + kk * 32;
            if (j < T / 4) {
                float4 c = cr[j];
                float4 k;
                k.x = expf((cm - c.x) * 10.f);   // overflows to +inf like reference
                k.y = expf((cm - c.y) * 10.f);
                k.z = expf((cm - c.z) * 10.f);
                k.w = expf((cm - c.w) * 10.f);
                skr[j] = k;
                // element-wise * (1/T) to match reference K@v0 overflow semantics
                acc += k.x * invT + k.y * invT + k.z * invT + k.w * invT;
            }
        }
#pragma unroll
        for (int o = 16; o; o >>= 1) acc += __shfl_down_sync(0xffffffffu, acc, o);
        if (lane == 0) {
            float u = 1.0f / (acc + 1e-6f);      // u after iteration 1
            su[w] = u;
            g_u[r] = u;
        }
        __syncthreads();
        if (tid < T) {
            // rows in ascending order -> fixed deterministic summation order
#pragma unroll
            for (int w2 = 0; w2 < RPB; w2++)
                vacc += sK[w2 * T + tid] * su[w2];   // inf*0 -> NaN, as reference
        }
        __syncthreads();                             // before next group reuses sK
    }
    if (tid < T)
        g_vpart[(b * CPB + blk) * T + tid] = vacc;
}

// ---------------- grid barrier (148 co-resident blocks) ----------------
__device__ __forceinline__ void grid_barrier() {
    __syncthreads();
    if (threadIdx.x == 0) {
        __threadfence();
        unsigned gen = g_bar_gen;
        if (atomicAdd(&g_bar_cnt, 1u) == gridDim.x - 1) {
            g_bar_cnt = 0;
            __threadfence();
            g_bar_gen = gen + 1;
        } else {
            while (g_bar_gen == gen) { __nanosleep(64); }
        }
        __threadfence();
    }
    __syncthreads();
}

__device__ __forceinline__ float kval(float cm, float c) { return expf((cm - c) * 10.f); }

// ---------------- kernel 4: v1 + certificate + flood output OR exact fallback ----------------
__global__ void __launch_bounds__(FTHR, 1) k_final(float* __restrict__ out) {
    __shared__ float s_buf[Q];
    __shared__ int   s_flag;
    const int tid  = threadIdx.x;
    const int gtid = blockIdx.x * FTHR + tid;
    const int lane = tid & 31;
    const int gw   = gtid >> 5;

    // ---- phase 1: v1 = 1/(colsum+eps) from 25 fixed-order partials; certificate; arange ----
    if (tid == 0) s_flag = 0;
    __syncthreads();
    bool anyNot = false;
    for (int i = gtid; i < B * T; i += FSTR) {
        int b = i / T, t = i - b * T;
        float s = 0.f;
#pragma unroll
        for (int k = 0; k < CPB; k++)
            s += g_vpart[(b * CPB + k) * T + t];
        float v = 1.0f / (s + 1e-6f);
        g_v[i] = v;
        out[B * T + i] = (float)t;                 // tgt_idx (arange)
        if (v == v) anyNot = true;                 // non-NaN exists
    }
    if (anyNot) s_flag = 1;
    __syncthreads();
    if (tid == 0 && s_flag) atomicOr(&g_flag, 1);
    grid_barrier();

    if (g_flag == 0) {
        // v1 all-NaN -> exact fixed point -> P all-NaN -> jnp.argmax = 0 everywhere
        for (int i = gtid; i < B * T; i += FSTR) out[i] = 0.f;
        return;
    }

    // ---- exact fallback: 19 more (u,v) pairs, K recomputed from C ----
    bool flood = false;
    for (int it = 1; it < ITERS; it++) {
        if (tid == 0) s_flag = 0;
        __syncthreads();
        anyNot = false;
        for (int r = gw; r < B * Q; r += FWARPS) {
            int b = r / Q;
            float cm = g_cmax[b];
            const float4* cr = (const float4*)(g_K + (size_t)r * T);
            const float4* v4 = (const float4*)(g_v + b * T);
            float acc = 0.f;
#pragma unroll
            for (int kk = 0; kk < 4; kk++) {
                int j = lane + kk * 32;
                if (j < T / 4) {
                    float4 c = cr[j]; float4 vv = v4[j];
                    acc += kval(cm, c.x) * vv.x + kval(cm, c.y) * vv.y
                         + kval(cm, c.z) * vv.z + kval(cm, c.w) * vv.w;
                }
            }
#pragma unroll
            for (int o = 16; o; o >>= 1) acc += __shfl_down_sync(0xffffffffu, acc, o);
            if (lane == 0) {
                float u = 1.0f / (acc + 1e-6f);
                g_u[r] = u;
                if (u == u) anyNot = true;
            }
        }
        if (anyNot) s_flag = 1;
        __syncthreads();
        if (tid == 0 && s_flag) atomicOr(&g_notnan[it], 1);
        grid_barrier();
        if (g_notnan[it] == 0) { flood = true; break; }   // all-NaN u fixed point

        // vpart: K^T u, 8 fixed chunks per block
        for (int k = 0; k < 8; k++) {
            int item = blockIdx.x * 8 + k;                 // 0..1183
            int b = item / QC, qc = item % QC;
            int q0 = qc * QCH, qn = min(QCH, Q - q0);
            __syncthreads();
            if (tid < qn) s_buf[tid] = g_u[b * Q + q0 + tid];
            __syncthreads();
            if (tid < T) {
                float cm = g_cmax[b];
                const float* cp = g_K + (size_t)(b * Q + q0) * T + tid;
                float a = 0.f;
                for (int i = 0; i < qn; i++)
                    a += kval(cm, cp[(size_t)i * T]) * s_buf[i];
                g_vpart[item * T + tid] = a;
            }
        }
        grid_barrier();
        for (int i = gtid; i < B * T; i += FSTR) {
            int b = i / T, t = i - b * T;
            float s = 0.f;
#pragma unroll
            for (int qc = 0; qc < QC; qc++)
                s += g_vpart[(b * QC + qc) * T + t];
            g_v[i] = 1.0f / (s + 1e-6f);
        }
        grid_barrier();
    }

    if (flood) {
        for (int i = gtid; i < B * T; i += FSTR) out[i] = 0.f;
        return;
    }

    // exact argmax over q of u*K*v with jnp NaN semantics (first occurrence)
    if (blockIdx.x < B) {
        int b = blockIdx.x;
        float cm = g_cmax[b];
        for (int i = tid; i < Q; i += FTHR) s_buf[i] = g_u[b * Q + i];
        __syncthreads();
        if (tid < T) {
            float v = g_v[b * T + tid];
            const float* cp = g_K + (size_t)b * Q * T + tid;
            float best = -INFINITY; int bq = 0; bool bnan = false;
            for (int q = 0; q < Q; q++) {
                float val = (s_buf[q] * kval(cm, cp[(size_t)q * T])) * v;
                bool vn = (val != val);
                if (!bnan && (vn || val > best)) { best = val; bq = q; bnan = vn; }
            }
            out[b * T + tid] = (float)bq;
        }
    }
}

// ---------------- launch ----------------
extern "C" void kernel_launch(void* const* d_in, const int* in_sizes, int n_in,
                              void* d_out, int out_size) {
    const float* logits = (const float*)d_in[0];   // (B,Q,NC) f32
    const float* pboxes = (const float*)d_in[1];   // (B,Q,4)  f32
    const int*   labels = (const int*)d_in[2];     // (B,T)    int32
    const float* tboxes = (const float*)d_in[3];   // (B,T,4)  f32
    float*       out    = (float*)d_out;           // f32: [0,BT)=src, [BT,2BT)=tgt

    k_prep<<<1, 64>>>();
    k_cost<<<3000, 512>>>(logits, pboxes, labels, tboxes);
    k_fuse<<<B * CPB, 640>>>();
    k_final<<<FBLK, FTHR>>>(out);
}